// round 4
// baseline (speedup 1.0000x reference)
#include <cuda_runtime.h>
#include <cstddef>

// Causal FlashAttention-2 forward, fp32 SIMT, k-vectorized LDS.128 version.
// Shapes: (B=4, H=16, S=2048, D=128) fp32 -> fp32.
//
// Per CTA: one q-tile of BM=128 rows for one (b,h); loop over BN=64 kv tiles.
// 256 threads.
//   QK phase : thread (rowg,colg) computes S[rowg+16i][colg+16j], i<8, j<4,
//              k in chunks of 4 via float4 LDS (strides % 4 == 0, conflict-free)
//   PV phase : thread computes O[rowg+16i][colg+16j], i<8, j<8, P read as float4
// Online softmax state (m, l, rescale) per-row in smem.

#define SEQ_D      128
#define BM         128
#define BN         64
#define NTH        256
#define QS_STRIDE  132   // %4==0 for LDS.128; superbank (33r+k/4)%8 = (r+k/4)%8
#define KS_STRIDE  132
#define SS_STRIDE  68

#define SM_SCALE   0.08838834764831843f  // 1/sqrt(128)

struct __align__(16) SmemLayout {
    float Qs[BM * QS_STRIDE];   // 67584 B
    float Ks[BN * KS_STRIDE];   // 33792 B
    float Vs[BN * SEQ_D];       // 32768 B
    float Ss[BM * SS_STRIDE];   // 34816 B
    float row_m[BM];
    float row_l[BM];
    float row_scale[BM];
};                               // ~166.6 KB

__global__ __launch_bounds__(NTH, 1)
void fa_causal_fwd(const float* __restrict__ Q,
                   const float* __restrict__ K,
                   const float* __restrict__ V,
                   float* __restrict__ O,
                   int seq)
{
    extern __shared__ char smem_raw[];
    SmemLayout& sm = *reinterpret_cast<SmemLayout*>(smem_raw);

    const int t  = threadIdx.x;
    const int bh = blockIdx.y;
    const int nqt = seq / BM;
    const int qt  = nqt - 1 - blockIdx.x;   // reversed: longest q-tiles first

    const size_t base = (size_t)bh * seq * SEQ_D;
    const float* Qb = Q + base + (size_t)qt * BM * SEQ_D;
    const float* Kb = K + base;
    const float* Vb = V + base;
    float*       Ob = O + base + (size_t)qt * BM * SEQ_D;

    // ---- load Q tile: LDG.128 coalesced, STS.128 conflict-free ----
    {
        const float4* Qv = reinterpret_cast<const float4*>(Qb);
        #pragma unroll
        for (int v = t; v < BM * SEQ_D / 4; v += NTH) {
            int r = v >> 5;            // / (128/4)
            int d4 = v & 31;
            float4 x = Qv[v];
            *reinterpret_cast<float4*>(&sm.Qs[r * QS_STRIDE + 4 * d4]) = x;
        }
    }
    if (t < BM) {
        sm.row_m[t] = -1e30f;
        sm.row_l[t] = 0.0f;
    }

    const int rowg = t >> 4;   // 0..15
    const int colg = t & 15;   // 0..15

    float acc[8][8];
    #pragma unroll
    for (int i = 0; i < 8; ++i)
        #pragma unroll
        for (int j = 0; j < 8; ++j)
            acc[i][j] = 0.0f;

    const int jmax = 2 * qt + 1;

    for (int j = 0; j <= jmax; ++j) {
        __syncthreads();   // previous PV done; safe to overwrite K/V tiles

        // ---- load K, V tiles (vectorized) ----
        {
            const float4* Kv = reinterpret_cast<const float4*>(Kb + (size_t)j * BN * SEQ_D);
            const float4* Vv = reinterpret_cast<const float4*>(Vb + (size_t)j * BN * SEQ_D);
            #pragma unroll
            for (int v = t; v < BN * SEQ_D / 4; v += NTH) {
                int r = v >> 5;
                int d4 = v & 31;
                float4 xk = Kv[v];
                float4 xv = Vv[v];
                *reinterpret_cast<float4*>(&sm.Ks[r * KS_STRIDE + 4 * d4]) = xk;
                *reinterpret_cast<float4*>(&sm.Vs[r * SEQ_D + 4 * d4])    = xv;
            }
        }
        __syncthreads();

        // ---- QK^T : 128x64 score tile, 8x4 micro-tile, k chunks of 4 ----
        float sreg[8][4];
        #pragma unroll
        for (int i = 0; i < 8; ++i)
            #pragma unroll
            for (int jj = 0; jj < 4; ++jj)
                sreg[i][jj] = 0.0f;

        #pragma unroll 2
        for (int k0 = 0; k0 < SEQ_D; k0 += 4) {
            float4 a[8], b[4];
            #pragma unroll
            for (int i = 0; i < 8; ++i)
                a[i] = *reinterpret_cast<const float4*>(
                         &sm.Qs[(rowg + 16 * i) * QS_STRIDE + k0]);
            #pragma unroll
            for (int jj = 0; jj < 4; ++jj)
                b[jj] = *reinterpret_cast<const float4*>(
                          &sm.Ks[(colg + 16 * jj) * KS_STRIDE + k0]);
            #pragma unroll
            for (int i = 0; i < 8; ++i)
                #pragma unroll
                for (int jj = 0; jj < 4; ++jj) {
                    float s = sreg[i][jj];
                    s = fmaf(a[i].x, b[jj].x, s);
                    s = fmaf(a[i].y, b[jj].y, s);
                    s = fmaf(a[i].z, b[jj].z, s);
                    s = fmaf(a[i].w, b[jj].w, s);
                    sreg[i][jj] = s;
                }
        }
        #pragma unroll
        for (int i = 0; i < 8; ++i)
            #pragma unroll
            for (int jj = 0; jj < 4; ++jj)
                sm.Ss[(rowg + 16 * i) * SS_STRIDE + (colg + 16 * jj)]
                    = sreg[i][jj] * SM_SCALE;
        __syncthreads();

        // ---- online softmax: 2 threads per row, 32 cols each ----
        {
            const int m  = t >> 1;           // 0..127
            const int c0 = (t & 1) * 32;
            const int qglob = qt * BM + m;
            const int kbase = j * BN + c0;
            float* srow = &sm.Ss[m * SS_STRIDE + c0];

            float mloc = -1e30f;
            #pragma unroll
            for (int c = 0; c < 32; ++c) {
                float s = srow[c];
                s = (kbase + c <= qglob) ? s : -1e30f;
                mloc = fmaxf(mloc, s);
            }
            mloc = fmaxf(mloc, __shfl_xor_sync(0xffffffffu, mloc, 1));

            const float mold = sm.row_m[m];
            const float mnew = fmaxf(mold, mloc);

            float suml = 0.0f;
            #pragma unroll
            for (int c = 0; c < 32; ++c) {
                float s = srow[c];
                bool ok = (kbase + c <= qglob);
                float p = ok ? __expf(s - mnew) : 0.0f;
                suml += p;
                srow[c] = p;
            }
            suml += __shfl_xor_sync(0xffffffffu, suml, 1);

            if ((t & 1) == 0) {
                const float sc = __expf(mold - mnew);
                sm.row_m[m]     = mnew;
                sm.row_l[m]     = sm.row_l[m] * sc + suml;
                sm.row_scale[m] = sc;
            }
        }
        __syncthreads();

        // ---- PV : O += P @ V (P via float4 along k, V scalar broadcast) ----
        float rs[8];
        #pragma unroll
        for (int i = 0; i < 8; ++i)
            rs[i] = sm.row_scale[rowg + 16 * i];
        #pragma unroll
        for (int i = 0; i < 8; ++i)
            #pragma unroll
            for (int jj = 0; jj < 8; ++jj)
                acc[i][jj] *= rs[i];

        #pragma unroll 2
        for (int k0 = 0; k0 < BN; k0 += 4) {
            float4 p4[8];
            #pragma unroll
            for (int i = 0; i < 8; ++i)
                p4[i] = *reinterpret_cast<const float4*>(
                          &sm.Ss[(rowg + 16 * i) * SS_STRIDE + k0]);
            #pragma unroll
            for (int kk = 0; kk < 4; ++kk) {
                float v[8];
                #pragma unroll
                for (int jj = 0; jj < 8; ++jj)
                    v[jj] = sm.Vs[(k0 + kk) * SEQ_D + colg + 16 * jj];
                #pragma unroll
                for (int i = 0; i < 8; ++i) {
                    float p = (kk == 0) ? p4[i].x :
                              (kk == 1) ? p4[i].y :
                              (kk == 2) ? p4[i].z : p4[i].w;
                    #pragma unroll
                    for (int jj = 0; jj < 8; ++jj)
                        acc[i][jj] = fmaf(p, v[jj], acc[i][jj]);
                }
            }
        }
    }

    // ---- epilogue: divide by l and store ----
    float linv[8];
    #pragma unroll
    for (int i = 0; i < 8; ++i)
        linv[i] = 1.0f / sm.row_l[rowg + 16 * i];

    #pragma unroll
    for (int i = 0; i < 8; ++i) {
        float* orow = Ob + (size_t)(rowg + 16 * i) * SEQ_D;
        #pragma unroll
        for (int jj = 0; jj < 8; ++jj)
            orow[colg + 16 * jj] = acc[i][jj] * linv[i];
    }
}

extern "C" void kernel_launch(void* const* d_in, const int* in_sizes, int n_in,
                              void* d_out, int out_size)
{
    const float* Q = (const float*)d_in[0];
    const float* K = (const float*)d_in[1];
    const float* V = (const float*)d_in[2];
    float*       O = (float*)d_out;

    const int seq = 2048;
    const int total = in_sizes[0];
    const int bh = total / (seq * SEQ_D);   // B*H = 64

    cudaFuncSetAttribute(fa_causal_fwd,
                         cudaFuncAttributeMaxDynamicSharedMemorySize,
                         (int)sizeof(SmemLayout));

    dim3 grid(seq / BM, bh);
    fa_causal_fwd<<<grid, NTH, sizeof(SmemLayout)>>>(Q, K, V, O, seq);
}

// round 7
// speedup vs baseline: 2.6726x; 2.6726x over previous
#include <cuda_runtime.h>
#include <cuda_bf16.h>
#include <cstdint>
#include <cstddef>

// Causal FlashAttention-2 fwd, warp-level bf16 mma.sync (sm_103-compatible),
// split-precision (x = hi + lo, 3-term products) for fp32-grade accuracy.
// (B=4,H=16,S=2048,D=128) fp32 -> fp32.
//
// Per CTA: BM=128 q rows (8 warps x 16), BN=64 kv tiles, D=128.
//  - Q scaled by 1/sqrt(D), split to bf16 hi/lo, fragments held in registers.
//  - K,V staged in smem bf16 hi/lo, natural [row][d] layout, stride 136
//    (ldmatrix row addrs -> distinct bank groups; STS coalesced).
//  - S = Q@K^T via mma.m16n8k16 (qh*kh + qh*kl + ql*kh), fp32 accum in regs.
//  - causal online softmax per lane-quad (shfl xor 1,2), no CTA sync.
//  - P fragments built in-register from S accums (C layout == A layout).
//  - O += P@V via mma with ldmatrix.x2.trans V fragments (ph*vh+ph*vl+pl*vh).

#define NTH 256
#define BM  128
#define BN  64
#define HD  128
#define KST 136                      // smem stride in bf16 elems
#define SM_SCALE 0.08838834764831843f

// smem byte offsets (all 1024-aligned)
#define OFF_QHI 0
#define OFF_QLO 34816
#define OFF_KHI 69632
#define OFF_KLO 87040
#define OFF_VHI 104448
#define OFF_VLO 121856
#define SMEM_TOTAL 139264

__device__ __forceinline__ uint32_t smem_u32(const void* p) {
    uint32_t a;
    asm("{ .reg .u64 t; cvta.to.shared.u64 t, %1; cvt.u32.u64 %0, t; }" : "=r"(a) : "l"(p));
    return a;
}
__device__ __forceinline__ void ldmx4(uint32_t r[4], uint32_t addr) {
    asm volatile("ldmatrix.sync.aligned.m8n8.x4.shared.b16 {%0,%1,%2,%3}, [%4];"
                 : "=r"(r[0]), "=r"(r[1]), "=r"(r[2]), "=r"(r[3]) : "r"(addr));
}
__device__ __forceinline__ void ldmx2(uint32_t r[2], uint32_t addr) {
    asm volatile("ldmatrix.sync.aligned.m8n8.x2.shared.b16 {%0,%1}, [%2];"
                 : "=r"(r[0]), "=r"(r[1]) : "r"(addr));
}
__device__ __forceinline__ void ldmx2t(uint32_t r[2], uint32_t addr) {
    asm volatile("ldmatrix.sync.aligned.m8n8.x2.trans.shared.b16 {%0,%1}, [%2];"
                 : "=r"(r[0]), "=r"(r[1]) : "r"(addr));
}
__device__ __forceinline__ void mma16816(float d[4], const uint32_t a[4], const uint32_t b[2]) {
    asm volatile("mma.sync.aligned.m16n8k16.row.col.f32.bf16.bf16.f32 "
                 "{%0,%1,%2,%3}, {%4,%5,%6,%7}, {%8,%9}, {%0,%1,%2,%3};"
                 : "+f"(d[0]), "+f"(d[1]), "+f"(d[2]), "+f"(d[3])
                 : "r"(a[0]), "r"(a[1]), "r"(a[2]), "r"(a[3]), "r"(b[0]), "r"(b[1]));
}
// split two floats into packed bf16x2 hi (truncation) and lo (exact remainder, rn)
__device__ __forceinline__ void packsplit(float x0, float x1, uint32_t& hi, uint32_t& lo) {
    uint32_t b0 = __float_as_uint(x0), b1 = __float_as_uint(x1);
    hi = (b0 >> 16) | (b1 & 0xFFFF0000u);
    float l0 = x0 - __uint_as_float(b0 & 0xFFFF0000u);
    float l1 = x1 - __uint_as_float(b1 & 0xFFFF0000u);
    lo = (uint32_t)__bfloat16_as_ushort(__float2bfloat16(l0))
       | ((uint32_t)__bfloat16_as_ushort(__float2bfloat16(l1)) << 16);
}
// split a float4 into uint2 hi / uint2 lo (packed bf16 pairs)
__device__ __forceinline__ void split4(float4 x, uint2& hi, uint2& lo) {
    packsplit(x.x, x.y, hi.x, lo.x);
    packsplit(x.z, x.w, hi.y, lo.y);
}

__global__ __launch_bounds__(NTH, 1)
void fa_mma(const float* __restrict__ Q, const float* __restrict__ K,
            const float* __restrict__ V, float* __restrict__ O, int seq)
{
    extern __shared__ char sm[];
    const uint32_t sb = smem_u32(sm);
    const int t = threadIdx.x;
    const int w = t >> 5, lane = t & 31;
    const int grp = lane >> 2, qd = lane & 3;     // mma row group / col pair
    const int lr = lane & 7;
    const int bh = blockIdx.y;
    const int nqt = seq / BM;
    const int qt = nqt - 1 - blockIdx.x;           // longest q-tiles first

    const size_t base = (size_t)bh * seq * HD;
    const float* Qb = Q + base + (size_t)qt * BM * HD;
    const float* Kb = K + base;
    const float* Vb = V + base;
    float*       Ob = O + base + (size_t)qt * BM * HD;

    // ---- stage Q (scaled, split) into smem ----
    {
        const float4* Qv = (const float4*)Qb;
        #pragma unroll
        for (int v = t; v < BM * 32; v += NTH) {
            int r = v >> 5, d = 4 * (v & 31);
            float4 x = Qv[v];
            x.x *= SM_SCALE; x.y *= SM_SCALE; x.z *= SM_SCALE; x.w *= SM_SCALE;
            uint2 hi, lo;
            split4(x, hi, lo);
            uint32_t off = (uint32_t)(r * KST + d) * 2u;
            *(uint2*)(sm + OFF_QHI + off) = hi;
            *(uint2*)(sm + OFF_QLO + off) = lo;
        }
    }
    __syncthreads();

    // ---- Q fragments -> registers (hi/lo), 8 k16 tiles ----
    uint32_t qhi[8][4], qlo[8][4];
    {
        int sel = lane >> 3;   // 0..3 (x4 matrix select)
        uint32_t rowoff = (uint32_t)((w * 16 + (sel & 1) * 8 + lr) * KST + (sel >> 1) * 8) * 2u;
        #pragma unroll
        for (int kt = 0; kt < 8; ++kt) {
            ldmx4(qhi[kt], sb + OFF_QHI + rowoff + 32u * kt);
            ldmx4(qlo[kt], sb + OFF_QLO + rowoff + 32u * kt);
        }
    }

    float oacc[16][4];
    #pragma unroll
    for (int i = 0; i < 16; ++i)
        #pragma unroll
        for (int c = 0; c < 4; ++c) oacc[i][c] = 0.0f;
    float m0 = -1e30f, m1 = -1e30f, l0 = 0.0f, l1 = 0.0f;

    const int qrow0 = qt * BM + w * 16 + grp;
    const int qrow1 = qrow0 + 8;
    const int jmax = 2 * qt + 1;

    // ldmatrix base addrs (per-lane), advanced by tile indices
    const int selk = (lane >> 3) & 1;
    const uint32_t kfrag_base = (uint32_t)(lr * KST + selk * 8) * 2u;            // + n8,kt
    const uint32_t vfrag_base = (uint32_t)((selk * 8 + lr) * KST) * 2u;          // + kt,n8

    for (int j = 0; j <= jmax; ++j) {
        __syncthreads();   // previous tile fully consumed

        // ---- stage K,V tile (split) ----
        {
            const float4* Kv = (const float4*)(Kb + (size_t)j * BN * HD);
            const float4* Vv = (const float4*)(Vb + (size_t)j * BN * HD);
            #pragma unroll
            for (int v = t; v < BN * 32; v += NTH) {
                int r = v >> 5, d = 4 * (v & 31);
                uint32_t off = (uint32_t)(r * KST + d) * 2u;
                uint2 hi, lo;
                split4(Kv[v], hi, lo);
                *(uint2*)(sm + OFF_KHI + off) = hi;
                *(uint2*)(sm + OFF_KLO + off) = lo;
                split4(Vv[v], hi, lo);
                *(uint2*)(sm + OFF_VHI + off) = hi;
                *(uint2*)(sm + OFF_VLO + off) = lo;
            }
        }
        __syncthreads();

        // ---- S = Q @ K^T (3-term split) ----
        float sacc[8][4];
        #pragma unroll
        for (int n8 = 0; n8 < 8; ++n8)
            #pragma unroll
            for (int c = 0; c < 4; ++c) sacc[n8][c] = 0.0f;

        #pragma unroll
        for (int kt = 0; kt < 8; ++kt) {
            #pragma unroll
            for (int n8 = 0; n8 < 8; ++n8) {
                uint32_t off = kfrag_base + (uint32_t)(8 * n8 * KST + 16 * kt) * 2u;
                uint32_t bh2[2], bl2[2];
                ldmx2(bh2, sb + OFF_KHI + off);
                ldmx2(bl2, sb + OFF_KLO + off);
                mma16816(sacc[n8], qhi[kt], bh2);
                mma16816(sacc[n8], qhi[kt], bl2);
                mma16816(sacc[n8], qlo[kt], bh2);
            }
        }

        // ---- causal online softmax (lane-quad local) ----
        float mx0 = m0, mx1 = m1;
        #pragma unroll
        for (int n8 = 0; n8 < 8; ++n8) {
            int c0 = j * BN + 8 * n8 + 2 * qd;
            float s0 = (c0     <= qrow0) ? sacc[n8][0] : -1e30f;
            float s1 = (c0 + 1 <= qrow0) ? sacc[n8][1] : -1e30f;
            float s2 = (c0     <= qrow1) ? sacc[n8][2] : -1e30f;
            float s3 = (c0 + 1 <= qrow1) ? sacc[n8][3] : -1e30f;
            sacc[n8][0] = s0; sacc[n8][1] = s1; sacc[n8][2] = s2; sacc[n8][3] = s3;
            mx0 = fmaxf(mx0, fmaxf(s0, s1));
            mx1 = fmaxf(mx1, fmaxf(s2, s3));
        }
        mx0 = fmaxf(mx0, __shfl_xor_sync(0xffffffffu, mx0, 1));
        mx0 = fmaxf(mx0, __shfl_xor_sync(0xffffffffu, mx0, 2));
        mx1 = fmaxf(mx1, __shfl_xor_sync(0xffffffffu, mx1, 1));
        mx1 = fmaxf(mx1, __shfl_xor_sync(0xffffffffu, mx1, 2));

        const float rsc0 = __expf(m0 - mx0);
        const float rsc1 = __expf(m1 - mx1);
        m0 = mx0; m1 = mx1;

        float sum0 = 0.0f, sum1 = 0.0f;
        #pragma unroll
        for (int n8 = 0; n8 < 8; ++n8) {
            float p0 = __expf(sacc[n8][0] - m0);
            float p1 = __expf(sacc[n8][1] - m0);
            float p2 = __expf(sacc[n8][2] - m1);
            float p3 = __expf(sacc[n8][3] - m1);
            sum0 += p0 + p1; sum1 += p2 + p3;
            sacc[n8][0] = p0; sacc[n8][1] = p1; sacc[n8][2] = p2; sacc[n8][3] = p3;
        }
        sum0 += __shfl_xor_sync(0xffffffffu, sum0, 1);
        sum0 += __shfl_xor_sync(0xffffffffu, sum0, 2);
        sum1 += __shfl_xor_sync(0xffffffffu, sum1, 1);
        sum1 += __shfl_xor_sync(0xffffffffu, sum1, 2);
        l0 = l0 * rsc0 + sum0;
        l1 = l1 * rsc1 + sum1;

        // rescale O accumulators
        #pragma unroll
        for (int i = 0; i < 16; ++i) {
            oacc[i][0] *= rsc0; oacc[i][1] *= rsc0;
            oacc[i][2] *= rsc1; oacc[i][3] *= rsc1;
        }

        // ---- O += P @ V (3-term split; P frags from S accums) ----
        #pragma unroll
        for (int kt = 0; kt < 4; ++kt) {
            uint32_t pah[4], pal[4];
            packsplit(sacc[2*kt][0],   sacc[2*kt][1],   pah[0], pal[0]);
            packsplit(sacc[2*kt][2],   sacc[2*kt][3],   pah[1], pal[1]);
            packsplit(sacc[2*kt+1][0], sacc[2*kt+1][1], pah[2], pal[2]);
            packsplit(sacc[2*kt+1][2], sacc[2*kt+1][3], pah[3], pal[3]);
            #pragma unroll
            for (int n8 = 0; n8 < 16; ++n8) {
                uint32_t off = vfrag_base + (uint32_t)(16 * kt * KST + 8 * n8) * 2u;
                uint32_t bh2[2], bl2[2];
                ldmx2t(bh2, sb + OFF_VHI + off);
                ldmx2t(bl2, sb + OFF_VLO + off);
                mma16816(oacc[n8], pah, bh2);
                mma16816(oacc[n8], pah, bl2);
                mma16816(oacc[n8], pal, bh2);
            }
        }
    }

    // ---- epilogue ----
    const float linv0 = 1.0f / l0;
    const float linv1 = 1.0f / l1;
    float* orow0 = Ob + (size_t)(w * 16 + grp) * HD;
    float* orow1 = orow0 + 8 * HD;
    #pragma unroll
    for (int n8 = 0; n8 < 16; ++n8) {
        int col = 8 * n8 + 2 * qd;
        float2 v0 = make_float2(oacc[n8][0] * linv0, oacc[n8][1] * linv0);
        float2 v1 = make_float2(oacc[n8][2] * linv1, oacc[n8][3] * linv1);
        *(float2*)(orow0 + col) = v0;
        *(float2*)(orow1 + col) = v1;
    }
}

extern "C" void kernel_launch(void* const* d_in, const int* in_sizes, int n_in,
                              void* d_out, int out_size)
{
    const float* Q = (const float*)d_in[0];
    const float* K = (const float*)d_in[1];
    const float* V = (const float*)d_in[2];
    float*       O = (float*)d_out;

    const int seq = 2048;
    const int total = in_sizes[0];
    const int bh = total / (seq * HD);   // 64

    cudaFuncSetAttribute(fa_mma, cudaFuncAttributeMaxDynamicSharedMemorySize, SMEM_TOTAL);
    dim3 grid(seq / BM, bh);
    fa_mma<<<grid, NTH, SMEM_TOTAL>>>(Q, K, V, O, seq);
}

// round 9
// speedup vs baseline: 2.8120x; 1.0521x over previous
#include <cuda_runtime.h>
#include <cuda_fp16.h>
#include <cstdint>
#include <cstddef>

// Causal FlashAttention-2 fwd, warp-level fp16 mma.sync (sm_103-compatible),
// split precision: QK 3-term (qh*kh+qh*kl+ql*kh, ~2^-22), PV 2-term
// (p_fp16*(vh+vl), ~2^-11 on P). fp32 accum everywhere.
// (B=4,H=16,S=2048,D=128) fp32 -> fp32.
//
// Per CTA: BM=128 q rows (8 warps x 16), BN=64 kv tiles, D=128.
// Double-buffered K/V smem; K(j+1)/V(j+1) prefetched into registers under the
// MMA phases; ONE __syncthreads per tile. ldmatrix x4 halves LDSM count.
// exp2-domain softmax (log2e folded into Q scale).

#define NTH 256
#define BM  128
#define BN  64
#define HD  128
#define KST 136                      // smem stride in fp16 elems (272B rows)
#define QSCALE 0.1275174538332464f   // (1/sqrt(128)) * log2(e)

// per-buffer layout (bytes): K hi/lo, V hi/lo, each 64*136*2 = 17408
#define B_KHI 0
#define B_KLO 17408
#define B_VHI 34816
#define B_VLO 52224
#define BUFSZ 69632
#define SMEM_TOTAL (2 * BUFSZ)       // 139264; Q staging reuses buffer 0 area
#define OFF_QHI 0
#define OFF_QLO 34816                // 128*136*2

__device__ __forceinline__ uint32_t smem_u32(const void* p) {
    uint32_t a;
    asm("{ .reg .u64 t; cvta.to.shared.u64 t, %1; cvt.u32.u64 %0, t; }" : "=r"(a) : "l"(p));
    return a;
}
__device__ __forceinline__ void ldmx4(uint32_t r[4], uint32_t addr) {
    asm volatile("ldmatrix.sync.aligned.m8n8.x4.shared.b16 {%0,%1,%2,%3}, [%4];"
                 : "=r"(r[0]), "=r"(r[1]), "=r"(r[2]), "=r"(r[3]) : "r"(addr));
}
__device__ __forceinline__ void ldmx4t(uint32_t r[4], uint32_t addr) {
    asm volatile("ldmatrix.sync.aligned.m8n8.x4.trans.shared.b16 {%0,%1,%2,%3}, [%4];"
                 : "=r"(r[0]), "=r"(r[1]), "=r"(r[2]), "=r"(r[3]) : "r"(addr));
}
__device__ __forceinline__ void mma16816(float d[4], const uint32_t a[4],
                                         uint32_t b0, uint32_t b1) {
    asm volatile("mma.sync.aligned.m16n8k16.row.col.f32.f16.f16.f32 "
                 "{%0,%1,%2,%3}, {%4,%5,%6,%7}, {%8,%9}, {%0,%1,%2,%3};"
                 : "+f"(d[0]), "+f"(d[1]), "+f"(d[2]), "+f"(d[3])
                 : "r"(a[0]), "r"(a[1]), "r"(a[2]), "r"(a[3]), "r"(b0), "r"(b1));
}
__device__ __forceinline__ uint32_t packh2(float x0, float x1) {
    __half2 h = __floats2half2_rn(x0, x1);
    return *reinterpret_cast<uint32_t*>(&h);
}
// fp16 split: hi = rn(x), lo = rn(x - hi)
__device__ __forceinline__ void packsplit(float x0, float x1, uint32_t& hi, uint32_t& lo) {
    __half h0 = __float2half_rn(x0), h1 = __float2half_rn(x1);
    hi = (uint32_t)__half_as_ushort(h0) | ((uint32_t)__half_as_ushort(h1) << 16);
    __half l0 = __float2half_rn(x0 - __half2float(h0));
    __half l1 = __float2half_rn(x1 - __half2float(h1));
    lo = (uint32_t)__half_as_ushort(l0) | ((uint32_t)__half_as_ushort(l1) << 16);
}
__device__ __forceinline__ void split4(float4 x, uint2& hi, uint2& lo) {
    packsplit(x.x, x.y, hi.x, lo.x);
    packsplit(x.z, x.w, hi.y, lo.y);
}

__global__ __launch_bounds__(NTH, 1)
void fa_mma(const float* __restrict__ Q, const float* __restrict__ K,
            const float* __restrict__ V, float* __restrict__ O, int seq)
{
    extern __shared__ char sm[];
    const uint32_t sb = smem_u32(sm);
    const int t = threadIdx.x;
    const int w = t >> 5, lane = t & 31;
    const int grp = lane >> 2, qd = lane & 3;
    const int lr = lane & 7;
    const int bh = blockIdx.y;
    const int nqt = seq / BM;
    const int qt = nqt - 1 - blockIdx.x;

    const size_t base = (size_t)bh * seq * HD;
    const float* Qb = Q + base + (size_t)qt * BM * HD;
    const float* Kb = K + base;
    const float* Vb = V + base;
    float*       Ob = O + base + (size_t)qt * BM * HD;

    // ---- stage Q (scaled by 1/sqrt(d)*log2e, fp16-split) into buffer-0 area ----
    {
        const float4* Qv = (const float4*)Qb;
        #pragma unroll
        for (int v = t; v < BM * 32; v += NTH) {
            int r = v >> 5, d = 4 * (v & 31);
            float4 x = Qv[v];
            x.x *= QSCALE; x.y *= QSCALE; x.z *= QSCALE; x.w *= QSCALE;
            uint2 hi, lo;
            split4(x, hi, lo);
            uint32_t off = (uint32_t)(r * KST + d) * 2u;
            *(uint2*)(sm + OFF_QHI + off) = hi;
            *(uint2*)(sm + OFF_QLO + off) = lo;
        }
    }
    __syncthreads();

    // ---- Q fragments -> registers, 8 k16 tiles ----
    uint32_t qhi[8][4], qlo[8][4];
    {
        int sel = lane >> 3;
        uint32_t rowoff = (uint32_t)((w * 16 + (sel & 1) * 8 + lr) * KST + (sel >> 1) * 8) * 2u;
        #pragma unroll
        for (int kt = 0; kt < 8; ++kt) {
            ldmx4(qhi[kt], sb + OFF_QHI + rowoff + 32u * kt);
            ldmx4(qlo[kt], sb + OFF_QLO + rowoff + 32u * kt);
        }
    }
    __syncthreads();   // Q region free; becomes buffer 0

    // ---- stage KV tile 0 into buffer 0 ----
    {
        const float4* Kv = (const float4*)Kb;
        const float4* Vv = (const float4*)Vb;
        #pragma unroll
        for (int v = t; v < BN * 32; v += NTH) {
            int r = v >> 5, d = 4 * (v & 31);
            uint32_t off = (uint32_t)(r * KST + d) * 2u;
            uint2 hi, lo;
            split4(Kv[v], hi, lo);
            *(uint2*)(sm + B_KHI + off) = hi;
            *(uint2*)(sm + B_KLO + off) = lo;
            split4(Vv[v], hi, lo);
            *(uint2*)(sm + B_VHI + off) = hi;
            *(uint2*)(sm + B_VLO + off) = lo;
        }
    }
    __syncthreads();

    float oacc[16][4];
    #pragma unroll
    for (int i = 0; i < 16; ++i)
        #pragma unroll
        for (int c = 0; c < 4; ++c) oacc[i][c] = 0.0f;
    float m0 = -1e30f, m1 = -1e30f, l0 = 0.0f, l1 = 0.0f;

    const int qrow0 = qt * BM + w * 16 + grp;
    const int qrow1 = qrow0 + 8;
    const int jmax = 2 * qt + 1;

    // per-lane ldmatrix x4 bases
    const uint32_t kfb = (uint32_t)((((lane >> 4) * 8) + lr) * KST + ((lane >> 3) & 1) * 8) * 2u;
    const uint32_t vfb = (uint32_t)((((lane >> 3) & 1) * 8 + lr) * KST + (lane >> 4) * 8) * 2u;

    // per-thread staging indices
    const int str = t >> 5, std_ = 4 * (t & 31);
    const uint32_t stoff = (uint32_t)(str * KST + std_) * 2u;

    for (int j = 0; j <= jmax; ++j) {
        const uint32_t cb = sb + (uint32_t)(j & 1) * BUFSZ;
        char* nb = sm + ((j + 1) & 1) * BUFSZ;
        const bool pf = (j < jmax);

        // ---- prefetch K(j+1) into registers (latency hidden by MMA1) ----
        float4 kr[8];
        if (pf) {
            const float4* Kn = (const float4*)(Kb + (size_t)(j + 1) * BN * HD);
            #pragma unroll
            for (int i = 0; i < 8; ++i) kr[i] = Kn[t + i * NTH];
        }

        // ---- MMA1: S = Q @ K^T (3-term fp16 split) ----
        float sacc[8][4];
        #pragma unroll
        for (int n8 = 0; n8 < 8; ++n8)
            #pragma unroll
            for (int c = 0; c < 4; ++c) sacc[n8][c] = 0.0f;

        #pragma unroll
        for (int kt = 0; kt < 8; ++kt) {
            #pragma unroll
            for (int n8p = 0; n8p < 4; ++n8p) {
                uint32_t off = kfb + (uint32_t)(16 * n8p * KST + 16 * kt) * 2u;
                uint32_t kh4[4], kl4[4];
                ldmx4(kh4, cb + B_KHI + off);
                ldmx4(kl4, cb + B_KLO + off);
                mma16816(sacc[2 * n8p],     qhi[kt], kh4[0], kh4[1]);
                mma16816(sacc[2 * n8p],     qhi[kt], kl4[0], kl4[1]);
                mma16816(sacc[2 * n8p],     qlo[kt], kh4[0], kh4[1]);
                mma16816(sacc[2 * n8p + 1], qhi[kt], kh4[2], kh4[3]);
                mma16816(sacc[2 * n8p + 1], qhi[kt], kl4[2], kl4[3]);
                mma16816(sacc[2 * n8p + 1], qlo[kt], kh4[2], kh4[3]);
            }
        }

        // ---- causal online softmax (exp2 domain, lane-quad local) ----
        float mx0 = m0, mx1 = m1;
        #pragma unroll
        for (int n8 = 0; n8 < 8; ++n8) {
            int c0 = j * BN + 8 * n8 + 2 * qd;
            float s0 = (c0     <= qrow0) ? sacc[n8][0] : -1e30f;
            float s1 = (c0 + 1 <= qrow0) ? sacc[n8][1] : -1e30f;
            float s2 = (c0     <= qrow1) ? sacc[n8][2] : -1e30f;
            float s3 = (c0 + 1 <= qrow1) ? sacc[n8][3] : -1e30f;
            sacc[n8][0] = s0; sacc[n8][1] = s1; sacc[n8][2] = s2; sacc[n8][3] = s3;
            mx0 = fmaxf(mx0, fmaxf(s0, s1));
            mx1 = fmaxf(mx1, fmaxf(s2, s3));
        }
        mx0 = fmaxf(mx0, __shfl_xor_sync(0xffffffffu, mx0, 1));
        mx0 = fmaxf(mx0, __shfl_xor_sync(0xffffffffu, mx0, 2));
        mx1 = fmaxf(mx1, __shfl_xor_sync(0xffffffffu, mx1, 1));
        mx1 = fmaxf(mx1, __shfl_xor_sync(0xffffffffu, mx1, 2));

        const float rsc0 = exp2f(m0 - mx0);
        const float rsc1 = exp2f(m1 - mx1);
        m0 = mx0; m1 = mx1;

        float sum0 = 0.0f, sum1 = 0.0f;
        #pragma unroll
        for (int n8 = 0; n8 < 8; ++n8) {
            float p0 = exp2f(sacc[n8][0] - m0);
            float p1 = exp2f(sacc[n8][1] - m0);
            float p2 = exp2f(sacc[n8][2] - m1);
            float p3 = exp2f(sacc[n8][3] - m1);
            sum0 += p0 + p1; sum1 += p2 + p3;
            sacc[n8][0] = p0; sacc[n8][1] = p1; sacc[n8][2] = p2; sacc[n8][3] = p3;
        }
        sum0 += __shfl_xor_sync(0xffffffffu, sum0, 1);
        sum0 += __shfl_xor_sync(0xffffffffu, sum0, 2);
        sum1 += __shfl_xor_sync(0xffffffffu, sum1, 1);
        sum1 += __shfl_xor_sync(0xffffffffu, sum1, 2);
        l0 = l0 * rsc0 + sum0;
        l1 = l1 * rsc1 + sum1;

        #pragma unroll
        for (int i = 0; i < 16; ++i) {
            oacc[i][0] *= rsc0; oacc[i][1] *= rsc0;
            oacc[i][2] *= rsc1; oacc[i][3] *= rsc1;
        }

        // ---- store K(j+1) split; prefetch V(j+1) (hidden by MMA2) ----
        float4 vr[8];
        if (pf) {
            #pragma unroll
            for (int i = 0; i < 8; ++i) {
                uint2 hi, lo;
                split4(kr[i], hi, lo);
                uint32_t off = stoff + (uint32_t)(i * 8 * KST) * 2u;
                *(uint2*)(nb + B_KHI + off) = hi;
                *(uint2*)(nb + B_KLO + off) = lo;
            }
            const float4* Vn = (const float4*)(Vb + (size_t)(j + 1) * BN * HD);
            #pragma unroll
            for (int i = 0; i < 8; ++i) vr[i] = Vn[t + i * NTH];
        }

        // ---- MMA2: O += P @ V (P single fp16, V hi/lo) ----
        #pragma unroll
        for (int kt = 0; kt < 4; ++kt) {
            uint32_t pa[4];
            pa[0] = packh2(sacc[2 * kt][0],     sacc[2 * kt][1]);
            pa[1] = packh2(sacc[2 * kt][2],     sacc[2 * kt][3]);
            pa[2] = packh2(sacc[2 * kt + 1][0], sacc[2 * kt + 1][1]);
            pa[3] = packh2(sacc[2 * kt + 1][2], sacc[2 * kt + 1][3]);
            #pragma unroll
            for (int n8p = 0; n8p < 8; ++n8p) {
                uint32_t off = vfb + (uint32_t)(16 * kt * KST + 16 * n8p) * 2u;
                uint32_t vh4[4], vl4[4];
                ldmx4t(vh4, cb + B_VHI + off);
                ldmx4t(vl4, cb + B_VLO + off);
                mma16816(oacc[2 * n8p],     pa, vh4[0], vh4[1]);
                mma16816(oacc[2 * n8p],     pa, vl4[0], vl4[1]);
                mma16816(oacc[2 * n8p + 1], pa, vh4[2], vh4[3]);
                mma16816(oacc[2 * n8p + 1], pa, vl4[2], vl4[3]);
            }
        }

        // ---- store V(j+1) split ----
        if (pf) {
            #pragma unroll
            for (int i = 0; i < 8; ++i) {
                uint2 hi, lo;
                split4(vr[i], hi, lo);
                uint32_t off = stoff + (uint32_t)(i * 8 * KST) * 2u;
                *(uint2*)(nb + B_VHI + off) = hi;
                *(uint2*)(nb + B_VLO + off) = lo;
            }
        }
        __syncthreads();
    }

    // ---- epilogue ----
    const float linv0 = 1.0f / l0;
    const float linv1 = 1.0f / l1;
    float* orow0 = Ob + (size_t)(w * 16 + grp) * HD;
    float* orow1 = orow0 + 8 * HD;
    #pragma unroll
    for (int n8 = 0; n8 < 16; ++n8) {
        int col = 8 * n8 + 2 * qd;
        *(float2*)(orow0 + col) = make_float2(oacc[n8][0] * linv0, oacc[n8][1] * linv0);
        *(float2*)(orow1 + col) = make_float2(oacc[n8][2] * linv1, oacc[n8][3] * linv1);
    }
}

extern "C" void kernel_launch(void* const* d_in, const int* in_sizes, int n_in,
                              void* d_out, int out_size)
{
    const float* Q = (const float*)d_in[0];
    const float* K = (const float*)d_in[1];
    const float* V = (const float*)d_in[2];
    float*       O = (float*)d_out;

    const int seq = 2048;
    const int total = in_sizes[0];
    const int bh = total / (seq * HD);   // 64

    cudaFuncSetAttribute(fa_mma, cudaFuncAttributeMaxDynamicSharedMemorySize, SMEM_TOTAL);
    dim3 grid(seq / BM, bh);
    fa_mma<<<grid, NTH, SMEM_TOTAL>>>(Q, K, V, O, seq);
}